// round 1
// baseline (speedup 1.0000x reference)
#include <cuda_runtime.h>

// Problem constants (DioLstm: B=4, NWORD=24, HID=512)
#define BD 4
#define NW 24
#define HD 512
#define H2 1024
#define H5 2560
#define NCELL (NW*NW)

// Chart state + precomputed per-cell projections (device globals; no allocs).
__device__ float g_chartH[BD*NCELL*HD];
__device__ float g_chartC[BD*NCELL*HD];
__device__ float g_chartS[BD*NCELL];
__device__ float g_Ui[BD*NCELL*H5];   // Wi @ h   per cell
__device__ float g_Us[BD*NCELL*H5];   // Ws @ h   per cell
__device__ float g_aL[BD*NCELL*H2];   // [h;c]^T @ Wbil per cell (left-child vector)
__device__ float g_WiT[HD*H5];        // Wi transposed: [k][o]
__device__ float g_WsT[HD*H5];
__device__ float g_bias[H5];          // bi + bs + ins_bias

__device__ __forceinline__ int cellIdx(int b, int left, int len) {
    return (b*NW + left)*NW + len;
}

__device__ __forceinline__ float sigf(float x) {
    // accurate-enough sigmoid: EX2 + RCP (MUFU x2), ~2ulp
    return __fdividef(1.0f, 1.0f + __expf(-x));
}
__device__ __forceinline__ float tanhx(float x) {
    // tanh(x) = 2/(1+exp(-2x)) - 1 ; saturates correctly at +/-inf exp
    return __fdividef(2.0f, 1.0f + __expf(-2.0f*x)) - 1.0f;
}

// ---------------------------------------------------------------------------
// Transpose Wi/Ws ([5H,H] row-major -> [H,5H]) so GEMM weight loads coalesce.
// grid (16, 80, 2), block (32, 8)
// ---------------------------------------------------------------------------
__global__ void transposeK(const float* __restrict__ Wi, const float* __restrict__ Ws) {
    __shared__ float tile[32][33];
    const float* src = blockIdx.z ? Ws : Wi;
    float* dst = blockIdx.z ? g_WsT : g_WiT;
    int r0 = blockIdx.y * 32;   // row in W  (o dim, 2560)
    int c0 = blockIdx.x * 32;   // col in W  (k dim, 512)
    #pragma unroll
    for (int i = threadIdx.y; i < 32; i += 8)
        tile[i][threadIdx.x] = src[(r0 + i)*HD + c0 + threadIdx.x];
    __syncthreads();
    #pragma unroll
    for (int i = threadIdx.y; i < 32; i += 8)
        dst[(c0 + i)*H5 + r0 + threadIdx.x] = tile[threadIdx.x][i];
}

// ---------------------------------------------------------------------------
// Init: leaves (chartH/C/S at len=0) + combined bias vector.
// grid 192 x 256 threads (covers 4*24*512 = 49152 leaf elements)
// ---------------------------------------------------------------------------
__global__ void initK(const float* __restrict__ seqt,
                      const float* __restrict__ bi,
                      const float* __restrict__ bs) {
    int idx = blockIdx.x*256 + threadIdx.x;
    if (idx < BD*NW*HD) {
        int i = idx % HD;
        int w = (idx / HD) % NW;
        int b = idx / (HD*NW);
        int c = cellIdx(b, w, 0);
        g_chartH[c*HD + i] = seqt[(b*NW + w)*H2 + i];
        g_chartC[c*HD + i] = seqt[(b*NW + w)*H2 + HD + i];
        if (i == 0) g_chartS[c] = 0.0f;
    }
    if (idx < H5) {
        float extra = (idx >= HD && idx < 3*HD) ? 1.0f : 0.0f;  // ins_bias forget slots
        g_bias[idx] = bi[idx] + bs[idx] + extra;
    }
}

// ---------------------------------------------------------------------------
// Per-cell projection GEMM for cells created at diagonal L (or leaves, L=0).
// Output space per cell: [Ui(2560) | Us(2560) | aL(1024)] = 6144.
// grid (24, ceil(M/CT)), 256 threads; thread owns 1 output col for CT cells.
// ---------------------------------------------------------------------------
template<int CT>
__global__ void projK(int L, int P, const float* __restrict__ Wbil) {
    int o = blockIdx.x*256 + threadIdx.x;       // 0..6143
    int M = BD*P;
    int cbase = blockIdx.y*CT;
    int nc = M - cbase; if (nc > CT) nc = CT;

    __shared__ float xs[CT][H2];                // [h;c] per cell
    for (int t = threadIdx.x; t < CT*H2; t += 256) {
        int c = t / H2, i = t % H2;
        float v = 0.0f;
        if (c < nc) {
            int cell = cbase + c;
            int b = cell / P, left = cell % P;
            int ci = cellIdx(b, left, L);
            v = (i < HD) ? g_chartH[ci*HD + i] : g_chartC[ci*HD + (i - HD)];
        }
        xs[c][i] = v;
    }
    __syncthreads();

    const float* W; int wcol, ncols, K;
    if (o < H5)        { W = g_WiT; wcol = o;        ncols = H5; K = HD; }
    else if (o < 2*H5) { W = g_WsT; wcol = o - H5;   ncols = H5; K = HD; }
    else               { W = Wbil;  wcol = o - 2*H5; ncols = H2; K = H2; }

    float acc[CT];
    #pragma unroll
    for (int c = 0; c < CT; c++) acc[c] = 0.0f;

    const float* wp = W + wcol;
    #pragma unroll 4
    for (int k = 0; k < K; k++) {
        float w = wp[(size_t)k * ncols];
        #pragma unroll
        for (int c = 0; c < CT; c++) acc[c] = fmaf(w, xs[c][k], acc[c]);
    }

    for (int c = 0; c < nc; c++) {
        int cell = cbase + c;
        int b = cell / P, left = cell % P;
        int ci = cellIdx(b, left, L);
        if (o < H5)        g_Ui[(size_t)ci*H5 + o]          = acc[c];
        else if (o < 2*H5) g_Us[(size_t)ci*H5 + (o - H5)]   = acc[c];
        else               g_aL[(size_t)ci*H2 + (o - 2*H5)] = acc[c];
    }
}

// ---------------------------------------------------------------------------
// Pairs kernel for diagonal L: compat + softmax + gated combine.
// grid = BD*P*SPLIT blocks of 256; each block owns span (b,left) and an
// e-chunk of size HD/SPLIT (split spreads MUFU work across SMs).
// ---------------------------------------------------------------------------
__global__ void pairsK(int L, int SPLIT, float* __restrict__ out) {
    int P = NW - L;
    int npair = BD*P;
    int pairId = blockIdx.x % npair;
    int s = blockIdx.x / npair;
    int b = pairId / P, left = pairId % P;
    int chunk = HD / SPLIT;
    int e0 = s * chunk;

    __shared__ float s_w[24];
    __shared__ float s_comp[24];
    __shared__ int   s_offL[24], s_offR[24];

    int tid = threadIdx.x, warp = tid >> 5, lane = tid & 31;

    // pass 1: compat_k = aL(left,k) . [rH;rC] + lS + rS  (one warp per k)
    for (int k = warp; k < L; k += 8) {
        int r = left + k + 1, rl = L - 1 - k;
        int cl = cellIdx(b, left, k), cr = cellIdx(b, r, rl);
        const float* a  = g_aL    + (size_t)cl*H2;
        const float* rh = g_chartH + (size_t)cr*HD;
        const float* rc = g_chartC + (size_t)cr*HD;
        float acc = 0.0f;
        for (int i = lane; i < HD; i += 32)
            acc = fmaf(a[i], rh[i], fmaf(a[HD + i], rc[i], acc));
        #pragma unroll
        for (int off = 16; off; off >>= 1)
            acc += __shfl_down_sync(0xffffffffu, acc, off);
        if (lane == 0) {
            s_comp[k] = acc + g_chartS[cl] + g_chartS[cr];
            s_offL[k] = cl; s_offR[k] = cr;
        }
    }
    __syncthreads();

    // softmax over k (warp 0; L <= 23)
    if (warp == 0) {
        float c = (lane < L) ? s_comp[lane] : -3.402823466e38f;
        float m = c;
        #pragma unroll
        for (int off = 16; off; off >>= 1)
            m = fmaxf(m, __shfl_xor_sync(0xffffffffu, m, off));
        float e = (lane < L) ? __expf(c - m) : 0.0f;
        float ssum = e;
        #pragma unroll
        for (int off = 16; off; off >>= 1)
            ssum += __shfl_xor_sync(0xffffffffu, ssum, off);
        float w = __fdividef(e, ssum);
        if (lane < L) s_w[lane] = w;
        float sn = (lane < L) ? w * c : 0.0f;
        #pragma unroll
        for (int off = 16; off; off >>= 1)
            sn += __shfl_xor_sync(0xffffffffu, sn, off);
        if (lane == 0 && s == 0) g_chartS[cellIdx(b, left, L)] = sn;
    }
    __syncthreads();

    // pass 2: gates + weighted combine over k for this block's e-chunk
    if (tid < chunk) {
        int e = e0 + tid;
        float b0 = g_bias[e],        b1 = g_bias[HD + e],  b2 = g_bias[2*HD + e];
        float b3 = g_bias[3*HD + e], b4 = g_bias[4*HD + e];
        float ah = 0.0f, ac = 0.0f;
        for (int k = 0; k < L; k++) {
            int cl = s_offL[k], cr = s_offR[k];
            const float* ui = g_Ui + (size_t)cl*H5;
            const float* us = g_Us + (size_t)cr*H5;
            float p0 = ui[e]        + us[e]        + b0;
            float p1 = ui[HD + e]   + us[HD + e]   + b1;
            float p2 = ui[2*HD + e] + us[2*HD + e] + b2;
            float p3 = ui[3*HD + e] + us[3*HD + e] + b3;
            float p4 = ui[4*HD + e] + us[4*HD + e] + b4;
            float lc = g_chartC[(size_t)cl*HD + e];
            float rc = g_chartC[(size_t)cr*HD + e];
            float ig = sigf(p0), lf = sigf(p1), rf = sigf(p2), og = sigf(p4);
            float gg = tanhx(p3);
            float mem = fmaf(lf, lc, fmaf(rf, rc, ig * gg));
            float hh = og * tanhx(mem);
            float w = s_w[k];
            ah = fmaf(w, hh, ah);
            ac = fmaf(w, mem, ac);
        }
        int cn = cellIdx(b, left, L);
        g_chartH[(size_t)cn*HD + e] = ah;
        g_chartC[(size_t)cn*HD + e] = ac;
        if (out) {                       // root diagonal: emit v = concat(h, c)
            out[b*H2 + e]      = ah;
            out[b*H2 + HD + e] = ac;
        }
    }
}

// ---------------------------------------------------------------------------
// Host side
// ---------------------------------------------------------------------------
static void launchProj(int L, int P, const float* Wbil) {
    int M = BD * P;
    dim3 g(6144 / 256, 1);
    if (M >= 56)      { g.y = (M + 7) / 8; projK<8><<<g, 256>>>(L, P, Wbil); }
    else if (M >= 28) { g.y = (M + 3) / 4; projK<4><<<g, 256>>>(L, P, Wbil); }
    else if (M >= 14) { g.y = (M + 1) / 2; projK<2><<<g, 256>>>(L, P, Wbil); }
    else              { g.y = M;           projK<1><<<g, 256>>>(L, P, Wbil); }
}

static int pickSplit(int P) {
    int np = BD * P;
    int s = 2;
    while (np * s < 160 && s < 8) s <<= 1;
    return s;
}

extern "C" void kernel_launch(void* const* d_in, const int* in_sizes, int n_in,
                              void* d_out, int out_size) {
    const float* seqt = (const float*)d_in[0];
    const float* Wi   = (const float*)d_in[1];
    const float* bi   = (const float*)d_in[2];
    const float* Ws   = (const float*)d_in[3];
    const float* bs   = (const float*)d_in[4];
    const float* Wbil = (const float*)d_in[5];
    float* out = (float*)d_out;

    transposeK<<<dim3(16, 80, 2), dim3(32, 8)>>>(Wi, Ws);
    initK<<<192, 256>>>(seqt, bi, bs);
    launchProj(0, NW, Wbil);                       // leaf projections (M = 96)

    for (int L = 1; L < NW; L++) {
        int P = NW - L;
        int SPLIT = pickSplit(P);
        pairsK<<<BD*P*SPLIT, 256>>>(L, SPLIT, (L == NW - 1) ? out : nullptr);
        if (L < NW - 1) launchProj(L, P, Wbil);
    }
}

// round 2
// speedup vs baseline: 1.0801x; 1.0801x over previous
#include <cuda_runtime.h>

// Problem constants (DioLstm: B=4, NWORD=24, HID=512)
#define BD 4
#define NW 24
#define HD 512
#define H2 1024
#define H5 2560

// Chart state + per-cell projections (device globals; no allocs).
__device__ float g_chartH[BD*NW*NW*HD];
__device__ float g_chartC[BD*NW*NW*HD];
__device__ float g_chartS[BD*NW*NW];
__device__ float g_Ui[BD*NW*NW*H5];   // Wi @ h   per cell
__device__ float g_Us[BD*NW*NW*H5];   // Ws @ h   per cell
__device__ float g_aL[BD*NW*NW*H2];   // [h;c]^T @ Wbil per cell
__device__ float g_WiT[HD*H5];        // Wi^T : [k][o]
__device__ float g_WsT[HD*H5];
__device__ float g_bias[H5];          // bi + bs + ins_bias

__device__ __forceinline__ int cellIdx(int b, int left, int len) {
    return (b*NW + left)*NW + len;
}

__device__ __forceinline__ float sigf(float x) {
    return __fdividef(1.0f, 1.0f + __expf(-x));
}
__device__ __forceinline__ float tanhx(float x) {
    return __fdividef(2.0f, 1.0f + __expf(-2.0f*x)) - 1.0f;
}

// ---------------------------------------------------------------------------
// Transpose Wi/Ws ([5H,H] -> [H,5H]) for coalesced GEMM weight loads.
// ---------------------------------------------------------------------------
__global__ void transposeK(const float* __restrict__ Wi, const float* __restrict__ Ws) {
    __shared__ float tile[32][33];
    const float* src = blockIdx.z ? Ws : Wi;
    float* dst = blockIdx.z ? g_WsT : g_WiT;
    int r0 = blockIdx.y * 32;
    int c0 = blockIdx.x * 32;
    #pragma unroll
    for (int i = threadIdx.y; i < 32; i += 8)
        tile[i][threadIdx.x] = src[(r0 + i)*HD + c0 + threadIdx.x];
    __syncthreads();
    #pragma unroll
    for (int i = threadIdx.y; i < 32; i += 8)
        dst[(c0 + i)*H5 + r0 + threadIdx.x] = tile[threadIdx.x][i];
}

// ---------------------------------------------------------------------------
// Leaves + combined bias.
// ---------------------------------------------------------------------------
__global__ void initK(const float* __restrict__ seqt,
                      const float* __restrict__ bi,
                      const float* __restrict__ bs) {
    int idx = blockIdx.x*256 + threadIdx.x;
    if (idx < BD*NW*HD) {
        int i = idx % HD;
        int w = (idx / HD) % NW;
        int b = idx / (HD*NW);
        int c = cellIdx(b, w, 0);
        g_chartH[(size_t)c*HD + i] = seqt[(b*NW + w)*H2 + i];
        g_chartC[(size_t)c*HD + i] = seqt[(b*NW + w)*H2 + HD + i];
        if (i == 0) g_chartS[c] = 0.0f;
    }
    if (idx < H5) {
        float extra = (idx >= HD && idx < 3*HD) ? 1.0f : 0.0f;
        g_bias[idx] = bi[idx] + bs[idx] + extra;
    }
}

// ---------------------------------------------------------------------------
// Per-cell projection GEMM, register-tiled 2 cols x 8 cells per thread.
// Output cols: [Ui 0..2559 | Us 2560..5119 | aL 5120..6143] = 6144 = 12 x 512.
// grid (12, ceil(M/8)), 256 threads. 4-deep weight prefetch, float2 loads.
// ---------------------------------------------------------------------------
__global__ void __launch_bounds__(256) projK(int L, int P, const float* __restrict__ Wbil) {
    const int colBase = blockIdx.x * 512;
    const int M = BD*P;
    const int cbase = blockIdx.y * 8;

    const float* W; int seg, ncols, K;
    if (colBase < H5)        { W = g_WiT; seg = 0;    ncols = H5; K = HD; }
    else if (colBase < 2*H5) { W = g_WsT; seg = H5;   ncols = H5; K = HD; }
    else                     { W = Wbil;  seg = 2*H5; ncols = H2; K = H2; }
    const bool bil = (K == H2);

    __shared__ float xs[8][H2];
    for (int t = threadIdx.x; t < 8*K; t += 256) {
        int c = t / K, i = t - c*K;
        float v = 0.0f;
        int cell = cbase + c;
        if (cell < M) {
            int b = cell / P, left = cell - b*P;
            int ci = cellIdx(b, left, L);
            if (!bil) v = g_chartH[(size_t)ci*HD + i];
            else      v = (i < HD) ? g_chartH[(size_t)ci*HD + i]
                                   : g_chartC[(size_t)ci*HD + (i - HD)];
        }
        xs[c][i] = v;
    }
    __syncthreads();

    const int wcol = (colBase - seg) + 2*threadIdx.x;
    const float* wp = W + wcol;
    const size_t ws = (size_t)ncols;

    float acc0[8], acc1[8];
    #pragma unroll
    for (int c = 0; c < 8; c++) { acc0[c] = 0.0f; acc1[c] = 0.0f; }

    float2 buf[4];
    #pragma unroll
    for (int j = 0; j < 4; j++) buf[j] = *(const float2*)(wp + (size_t)j * ws);

    for (int k = 0; k < K; k += 4) {
        float2 cur[4];
        #pragma unroll
        for (int j = 0; j < 4; j++) cur[j] = buf[j];
        if (k + 4 < K) {
            #pragma unroll
            for (int j = 0; j < 4; j++)
                buf[j] = *(const float2*)(wp + (size_t)(k + 4 + j) * ws);
        }
        #pragma unroll
        for (int kk = 0; kk < 4; kk++) {
            float wx = cur[kk].x, wy = cur[kk].y;
            #pragma unroll
            for (int c = 0; c < 8; c++) {
                float x = xs[c][k + kk];
                acc0[c] = fmaf(wx, x, acc0[c]);
                acc1[c] = fmaf(wy, x, acc1[c]);
            }
        }
    }

    float* dst; size_t stride;
    if (seg == 0)       { dst = g_Ui; stride = H5; }
    else if (seg == H5) { dst = g_Us; stride = H5; }
    else                { dst = g_aL; stride = H2; }

    #pragma unroll
    for (int c = 0; c < 8; c++) {
        int cell = cbase + c;
        if (cell < M) {
            int b = cell / P, left = cell - b*P;
            int ci = cellIdx(b, left, L);
            *(float2*)(dst + (size_t)ci*stride + wcol) = make_float2(acc0[c], acc1[c]);
        }
    }
}

// ---------------------------------------------------------------------------
// Pairs kernel: compat + softmax + gated combine.
// grid = BD*P*SPLIT blocks of (HD/SPLIT) threads; block owns span + e-chunk.
// ---------------------------------------------------------------------------
__global__ void pairsK(int L, int SPLIT, float* __restrict__ out) {
    const int P = NW - L;
    const int npair = BD*P;
    const int pairId = blockIdx.x % npair;
    const int s = blockIdx.x / npair;
    const int b = pairId / P, left = pairId - b*P;
    const int chunk = blockDim.x;          // HD / SPLIT
    const int e0 = s * chunk;

    __shared__ float s_w[24];
    __shared__ float s_comp[24];
    __shared__ int   s_offL[24], s_offR[24];

    const int tid = threadIdx.x, warp = tid >> 5, lane = tid & 31;
    const int nw = blockDim.x >> 5;

    // pass 1: compat_k = aL(left,k) . [rH;rC] + lS + rS
    for (int k = warp; k < L; k += nw) {
        int r = left + k + 1, rl = L - 1 - k;
        int cl = cellIdx(b, left, k), cr = cellIdx(b, r, rl);
        const float* a  = g_aL     + (size_t)cl*H2;
        const float* rh = g_chartH + (size_t)cr*HD;
        const float* rc = g_chartC + (size_t)cr*HD;
        float acc = 0.0f;
        for (int i = lane; i < HD; i += 32)
            acc = fmaf(a[i], rh[i], fmaf(a[HD + i], rc[i], acc));
        #pragma unroll
        for (int off = 16; off; off >>= 1)
            acc += __shfl_down_sync(0xffffffffu, acc, off);
        if (lane == 0) {
            s_comp[k] = acc + g_chartS[cl] + g_chartS[cr];
            s_offL[k] = cl; s_offR[k] = cr;
        }
    }
    __syncthreads();

    // softmax over k (warp 0)
    if (warp == 0) {
        float c = (lane < L) ? s_comp[lane] : -3.402823466e38f;
        float m = c;
        #pragma unroll
        for (int off = 16; off; off >>= 1)
            m = fmaxf(m, __shfl_xor_sync(0xffffffffu, m, off));
        float e = (lane < L) ? __expf(c - m) : 0.0f;
        float ssum = e;
        #pragma unroll
        for (int off = 16; off; off >>= 1)
            ssum += __shfl_xor_sync(0xffffffffu, ssum, off);
        float w = __fdividef(e, ssum);
        if (lane < L) s_w[lane] = w;
        float sn = (lane < L) ? w * c : 0.0f;
        #pragma unroll
        for (int off = 16; off; off >>= 1)
            sn += __shfl_xor_sync(0xffffffffu, sn, off);
        if (lane == 0 && s == 0) g_chartS[cellIdx(b, left, L)] = sn;
    }
    __syncthreads();

    // pass 2: gates + weighted combine for this block's e-chunk
    {
        int e = e0 + tid;
        float b0 = g_bias[e],        b1 = g_bias[HD + e],  b2 = g_bias[2*HD + e];
        float b3 = g_bias[3*HD + e], b4 = g_bias[4*HD + e];
        float ah = 0.0f, ac = 0.0f;
        for (int k = 0; k < L; k++) {
            int cl = s_offL[k], cr = s_offR[k];
            const float* ui = g_Ui + (size_t)cl*H5;
            const float* us = g_Us + (size_t)cr*H5;
            float p0 = ui[e]        + us[e]        + b0;
            float p1 = ui[HD + e]   + us[HD + e]   + b1;
            float p2 = ui[2*HD + e] + us[2*HD + e] + b2;
            float p3 = ui[3*HD + e] + us[3*HD + e] + b3;
            float p4 = ui[4*HD + e] + us[4*HD + e] + b4;
            float lc = g_chartC[(size_t)cl*HD + e];
            float rc = g_chartC[(size_t)cr*HD + e];
            float ig = sigf(p0), lf = sigf(p1), rf = sigf(p2), og = sigf(p4);
            float gg = tanhx(p3);
            float mem = fmaf(lf, lc, fmaf(rf, rc, ig * gg));
            float hh = og * tanhx(mem);
            float w = s_w[k];
            ah = fmaf(w, hh, ah);
            ac = fmaf(w, mem, ac);
        }
        int cn = cellIdx(b, left, L);
        g_chartH[(size_t)cn*HD + e] = ah;
        g_chartC[(size_t)cn*HD + e] = ac;
        if (out) {
            out[b*H2 + e]      = ah;
            out[b*H2 + HD + e] = ac;
        }
    }
}

// ---------------------------------------------------------------------------
// Host side
// ---------------------------------------------------------------------------
static void launchProj(int L, int P, const float* Wbil) {
    int M = BD * P;
    dim3 g(12, (M + 7) / 8);
    projK<<<g, 256>>>(L, P, Wbil);
}

static int pickSplit(int P) {
    int np = BD * P;
    if (np >= 64) return 4;   // chunk 128, blocks 256..368
    return 8;                 // chunk 64,  blocks 32P
}

extern "C" void kernel_launch(void* const* d_in, const int* in_sizes, int n_in,
                              void* d_out, int out_size) {
    const float* seqt = (const float*)d_in[0];
    const float* Wi   = (const float*)d_in[1];
    const float* bi   = (const float*)d_in[2];
    const float* Ws   = (const float*)d_in[3];
    const float* bs   = (const float*)d_in[4];
    const float* Wbil = (const float*)d_in[5];
    float* out = (float*)d_out;

    transposeK<<<dim3(16, 80, 2), dim3(32, 8)>>>(Wi, Ws);
    initK<<<192, 256>>>(seqt, bi, bs);
    launchProj(0, NW, Wbil);                       // leaf projections (M = 96)

    for (int L = 1; L < NW; L++) {
        int P = NW - L;
        int SPLIT = pickSplit(P);
        pairsK<<<BD*P*SPLIT, HD/SPLIT>>>(L, SPLIT, (L == NW - 1) ? out : nullptr);
        if (L < NW - 1) launchProj(L, P, Wbil);
    }
}

// round 3
// speedup vs baseline: 1.1889x; 1.1008x over previous
#include <cuda_runtime.h>

// Problem constants (DioLstm: B=4, NWORD=24, HID=512)
#define BD 4
#define NW 24
#define HD 512
#define H2 1024
#define H5 2560
#define KPAD 8

// Chart state + per-cell projections (device globals; no allocs).
__device__ float g_chartH[BD*NW*NW*HD];
__device__ float g_chartC[BD*NW*NW*HD];
__device__ float g_chartS[BD*NW*NW];
__device__ float g_Ui[BD*NW*NW*H5];          // Wi @ h   per cell
__device__ float g_Us[BD*NW*NW*H5];          // Ws @ h   per cell
__device__ float g_aL[BD*NW*NW*H2];          // [h;c]^T @ Wbil per cell
__device__ float g_WiT[(HD+KPAD)*H5];        // Wi^T : [k][o], K-padded
__device__ float g_WsT[(HD+KPAD)*H5];
__device__ float g_Wb [(H2+KPAD)*H2];        // Wbil copy, K-padded
__device__ float g_bias[H5];                 // bi + bs + ins_bias

__device__ __forceinline__ int cellIdx(int b, int left, int len) {
    return (b*NW + left)*NW + len;
}

__device__ __forceinline__ float sigf(float x) {
    return __fdividef(1.0f, 1.0f + __expf(-x));
}
__device__ __forceinline__ float tanhx(float x) {
    return __fdividef(2.0f, 1.0f + __expf(-2.0f*x)) - 1.0f;
}

// ---------------------------------------------------------------------------
// Transpose one weight matrix ([5H,H] -> [H,5H]); separate launch per matrix
// (also shifts the fixed ncu -s 5 capture onto projK(L=0)).
// ---------------------------------------------------------------------------
__global__ void transposeK(const float* __restrict__ W, int which) {
    __shared__ float tile[32][33];
    float* dst = which ? g_WsT : g_WiT;
    int r0 = blockIdx.y * 32;   // o dim (2560)
    int c0 = blockIdx.x * 32;   // k dim (512)
    #pragma unroll
    for (int i = threadIdx.y; i < 32; i += 8)
        tile[i][threadIdx.x] = W[(r0 + i)*HD + c0 + threadIdx.x];
    __syncthreads();
    #pragma unroll
    for (int i = threadIdx.y; i < 32; i += 8)
        dst[(c0 + i)*H5 + r0 + threadIdx.x] = tile[threadIdx.x][i];
}

// Copy half of Wbil into the K-padded g_Wb (two launches).
__global__ void copyWbK(const float* __restrict__ Wbil, int half) {
    int idx = (half * (H2*H2/2)) + blockIdx.x*256 + threadIdx.x;
    // row-major [k][o]; padding rows beyond H2 left as-is (never used in math)
    g_Wb[idx] = Wbil[idx];
}

// ---------------------------------------------------------------------------
// Leaves + combined bias.
// ---------------------------------------------------------------------------
__global__ void initK(const float* __restrict__ seqt,
                      const float* __restrict__ bi,
                      const float* __restrict__ bs) {
    int idx = blockIdx.x*256 + threadIdx.x;
    if (idx < BD*NW*HD) {
        int i = idx % HD;
        int w = (idx / HD) % NW;
        int b = idx / (HD*NW);
        int c = cellIdx(b, w, 0);
        g_chartH[(size_t)c*HD + i] = seqt[(b*NW + w)*H2 + i];
        g_chartC[(size_t)c*HD + i] = seqt[(b*NW + w)*H2 + HD + i];
        if (i == 0) g_chartS[c] = 0.0f;
    }
    if (idx < H5) {
        float extra = (idx >= HD && idx < 3*HD) ? 1.0f : 0.0f;
        g_bias[idx] = bi[idx] + bs[idx] + extra;
    }
}

// ---------------------------------------------------------------------------
// Per-cell projection GEMM, 2 cols x CT cells per thread, branch-free
// 4-deep K prefetch (padded weights), float4 smem activation loads.
// Output cols: [Ui 0..2559 | Us 2560..5119 | aL 5120..6143] = 12 x 512.
// grid (12, ceil(M/CT)), 256 threads.
// ---------------------------------------------------------------------------
template<int CT>
__global__ void __launch_bounds__(256) projK(int L, int P) {
    const int colBase = blockIdx.x * 512;
    const int M = BD*P;
    const int cbase = blockIdx.y * CT;

    const float* W; int seg, ncols, K;
    if (colBase < H5)        { W = g_WiT; seg = 0;    ncols = H5; K = HD; }
    else if (colBase < 2*H5) { W = g_WsT; seg = H5;   ncols = H5; K = HD; }
    else                     { W = g_Wb;  seg = 2*H5; ncols = H2; K = H2; }
    const bool bil = (K == H2);

    __shared__ float xs[CT][H2];
    for (int t = threadIdx.x; t < CT*K; t += 256) {
        int c = t / K, i = t - c*K;
        float v = 0.0f;
        int cell = cbase + c;
        if (cell < M) {
            int b = cell / P, left = cell - b*P;
            int ci = cellIdx(b, left, L);
            if (!bil) v = g_chartH[(size_t)ci*HD + i];
            else      v = (i < HD) ? g_chartH[(size_t)ci*HD + i]
                                   : g_chartC[(size_t)ci*HD + (i - HD)];
        }
        xs[c][i] = v;
    }
    __syncthreads();

    const int wcol = (colBase - seg) + 2*threadIdx.x;
    const float* wp = W + wcol;
    const size_t ws = (size_t)ncols;

    float acc0[CT], acc1[CT];
    #pragma unroll
    for (int c = 0; c < CT; c++) { acc0[c] = 0.0f; acc1[c] = 0.0f; }

    float2 buf[4];
    #pragma unroll
    for (int j = 0; j < 4; j++)
        buf[j] = *(const float2*)(wp + (size_t)j * ws);

    for (int k = 0; k < K; k += 4) {
        // next batch (always in-bounds thanks to K padding)
        float2 nxt[4];
        #pragma unroll
        for (int j = 0; j < 4; j++)
            nxt[j] = *(const float2*)(wp + (size_t)(k + 4 + j) * ws);

        float4 xv[CT];
        #pragma unroll
        for (int c = 0; c < CT; c++)
            xv[c] = *(const float4*)&xs[c][k];

        #pragma unroll
        for (int kk = 0; kk < 4; kk++) {
            float wx = buf[kk].x, wy = buf[kk].y;
            #pragma unroll
            for (int c = 0; c < CT; c++) {
                float x = (kk == 0) ? xv[c].x : (kk == 1) ? xv[c].y
                        : (kk == 2) ? xv[c].z : xv[c].w;
                acc0[c] = fmaf(wx, x, acc0[c]);
                acc1[c] = fmaf(wy, x, acc1[c]);
            }
        }
        #pragma unroll
        for (int j = 0; j < 4; j++) buf[j] = nxt[j];
    }

    float* dst; size_t stride;
    if (seg == 0)       { dst = g_Ui; stride = H5; }
    else if (seg == H5) { dst = g_Us; stride = H5; }
    else                { dst = g_aL; stride = H2; }

    #pragma unroll
    for (int c = 0; c < CT; c++) {
        int cell = cbase + c;
        if (cell < M) {
            int b = cell / P, left = cell - b*P;
            int ci = cellIdx(b, left, L);
            *(float2*)(dst + (size_t)ci*stride + wcol) = make_float2(acc0[c], acc1[c]);
        }
    }
}

// ---------------------------------------------------------------------------
// Pairs kernel: compat + softmax + gated combine.
// grid = BD*P*SPLIT blocks of (HD/SPLIT) threads; block owns span + e-chunk.
// ---------------------------------------------------------------------------
__global__ void pairsK(int L, int SPLIT, float* __restrict__ out) {
    const int P = NW - L;
    const int npair = BD*P;
    const int pairId = blockIdx.x % npair;
    const int s = blockIdx.x / npair;
    const int b = pairId / P, left = pairId - b*P;
    const int chunk = blockDim.x;
    const int e0 = s * chunk;

    __shared__ float s_w[24];
    __shared__ float s_comp[24];
    __shared__ int   s_offL[24], s_offR[24];

    const int tid = threadIdx.x, warp = tid >> 5, lane = tid & 31;
    const int nw = blockDim.x >> 5;

    // pass 1: compat_k = aL(left,k) . [rH;rC] + lS + rS
    for (int k = warp; k < L; k += nw) {
        int r = left + k + 1, rl = L - 1 - k;
        int cl = cellIdx(b, left, k), cr = cellIdx(b, r, rl);
        const float* a  = g_aL     + (size_t)cl*H2;
        const float* rh = g_chartH + (size_t)cr*HD;
        const float* rc = g_chartC + (size_t)cr*HD;
        float acc = 0.0f;
        for (int i = lane; i < HD; i += 32)
            acc = fmaf(a[i], rh[i], fmaf(a[HD + i], rc[i], acc));
        #pragma unroll
        for (int off = 16; off; off >>= 1)
            acc += __shfl_down_sync(0xffffffffu, acc, off);
        if (lane == 0) {
            s_comp[k] = acc + g_chartS[cl] + g_chartS[cr];
            s_offL[k] = cl; s_offR[k] = cr;
        }
    }
    __syncthreads();

    // softmax over k (warp 0)
    if (warp == 0) {
        float c = (lane < L) ? s_comp[lane] : -3.402823466e38f;
        float m = c;
        #pragma unroll
        for (int off = 16; off; off >>= 1)
            m = fmaxf(m, __shfl_xor_sync(0xffffffffu, m, off));
        float e = (lane < L) ? __expf(c - m) : 0.0f;
        float ssum = e;
        #pragma unroll
        for (int off = 16; off; off >>= 1)
            ssum += __shfl_xor_sync(0xffffffffu, ssum, off);
        float w = __fdividef(e, ssum);
        if (lane < L) s_w[lane] = w;
        float sn = (lane < L) ? w * c : 0.0f;
        #pragma unroll
        for (int off = 16; off; off >>= 1)
            sn += __shfl_xor_sync(0xffffffffu, sn, off);
        if (lane == 0 && s == 0) g_chartS[cellIdx(b, left, L)] = sn;
    }
    __syncthreads();

    // pass 2: gates + weighted combine for this block's e-chunk
    {
        int e = e0 + tid;
        float b0 = g_bias[e],        b1 = g_bias[HD + e],  b2 = g_bias[2*HD + e];
        float b3 = g_bias[3*HD + e], b4 = g_bias[4*HD + e];
        float ah = 0.0f, ac = 0.0f;
        for (int k = 0; k < L; k++) {
            int cl = s_offL[k], cr = s_offR[k];
            const float* ui = g_Ui + (size_t)cl*H5;
            const float* us = g_Us + (size_t)cr*H5;
            float p0 = ui[e]        + us[e]        + b0;
            float p1 = ui[HD + e]   + us[HD + e]   + b1;
            float p2 = ui[2*HD + e] + us[2*HD + e] + b2;
            float p3 = ui[3*HD + e] + us[3*HD + e] + b3;
            float p4 = ui[4*HD + e] + us[4*HD + e] + b4;
            float lc = g_chartC[(size_t)cl*HD + e];
            float rc = g_chartC[(size_t)cr*HD + e];
            float ig = sigf(p0), lf = sigf(p1), rf = sigf(p2), og = sigf(p4);
            float gg = tanhx(p3);
            float mem = fmaf(lf, lc, fmaf(rf, rc, ig * gg));
            float hh = og * tanhx(mem);
            float w = s_w[k];
            ah = fmaf(w, hh, ah);
            ac = fmaf(w, mem, ac);
        }
        int cn = cellIdx(b, left, L);
        g_chartH[(size_t)cn*HD + e] = ah;
        g_chartC[(size_t)cn*HD + e] = ac;
        if (out) {
            out[b*H2 + e]      = ah;
            out[b*H2 + HD + e] = ac;
        }
    }
}

// ---------------------------------------------------------------------------
// Host side
// ---------------------------------------------------------------------------
static void launchProj(int L, int P) {
    int M = BD * P;
    if (M >= 80)      projK<8><<<dim3(12, (M + 7) / 8), 256>>>(L, P);
    else if (M >= 32) projK<4><<<dim3(12, (M + 3) / 4), 256>>>(L, P);
    else if (M >= 16) projK<2><<<dim3(12, (M + 1) / 2), 256>>>(L, P);
    else              projK<1><<<dim3(12, M),           256>>>(L, P);
}

static int pickSplit(int P) {
    int np = BD * P;
    if (np >= 64) return 4;   // chunk 128
    return 8;                 // chunk 64
}

extern "C" void kernel_launch(void* const* d_in, const int* in_sizes, int n_in,
                              void* d_out, int out_size) {
    const float* seqt = (const float*)d_in[0];
    const float* Wi   = (const float*)d_in[1];
    const float* bi   = (const float*)d_in[2];
    const float* Ws   = (const float*)d_in[3];
    const float* bs   = (const float*)d_in[4];
    const float* Wbil = (const float*)d_in[5];
    float* out = (float*)d_out;

    // 5 setup launches => ncu (-s 5 -c 1) captures launch #6 = projK(L=0, M=96)
    transposeK<<<dim3(16, 80), dim3(32, 8)>>>(Wi, 0);
    transposeK<<<dim3(16, 80), dim3(32, 8)>>>(Ws, 1);
    initK<<<192, 256>>>(seqt, bi, bs);
    copyWbK<<<(H2*H2/2)/256, 256>>>(Wbil, 0);
    copyWbK<<<(H2*H2/2)/256, 256>>>(Wbil, 1);

    launchProj(0, NW);                             // leaf projections (M = 96)

    for (int L = 1; L < NW; L++) {
        int P = NW - L;
        int SPLIT = pickSplit(P);
        pairsK<<<BD*P*SPLIT, HD/SPLIT>>>(L, SPLIT, (L == NW - 1) ? out : nullptr);
        if (L < NW - 1) launchProj(L, P);
    }
}

// round 4
// speedup vs baseline: 1.2979x; 1.0916x over previous
#include <cuda_runtime.h>

// Problem constants (DioLstm: B=4, NWORD=24, HID=512)
#define BD 4
#define NW 24
#define HD 512
#define H2 1024
#define H5 2560
#define KPAD 16

// Chart state + per-cell projections (device globals; no allocs).
__device__ float g_chartH[BD*NW*NW*HD];
__device__ float g_chartC[BD*NW*NW*HD];
__device__ float g_chartS[BD*NW*NW];
__device__ float g_Ui[BD*NW*NW*H5];          // Wi @ h   per cell
__device__ float g_Us[BD*NW*NW*H5];          // Ws @ h   per cell
__device__ float g_aL[BD*NW*NW*H2];          // [h;c]^T @ Wbil per cell
__device__ float g_WiT[(HD+KPAD)*H5];        // Wi^T : [k][o], K-padded
__device__ float g_WsT[(HD+KPAD)*H5];
__device__ float g_Wb [(H2+KPAD)*H2];        // Wbil copy, K-padded
__device__ float g_bias[H5];                 // bi + bs + ins_bias

__device__ __forceinline__ int cellIdx(int b, int left, int len) {
    return (b*NW + left)*NW + len;
}

__device__ __forceinline__ float sigf(float x) {
    return __fdividef(1.0f, 1.0f + __expf(-x));
}
__device__ __forceinline__ float tanhx(float x) {
    return __fdividef(2.0f, 1.0f + __expf(-2.0f*x)) - 1.0f;
}

// ---------------------------------------------------------------------------
// Launch #0: transpose Wi/Ws ([5H,H] -> [H,5H]) into padded arrays.
// ---------------------------------------------------------------------------
__global__ void transposeK(const float* __restrict__ Wi, const float* __restrict__ Ws) {
    __shared__ float tile[32][33];
    const float* src = blockIdx.z ? Ws : Wi;
    float* dst = blockIdx.z ? g_WsT : g_WiT;
    int r0 = blockIdx.y * 32;   // o dim (2560)
    int c0 = blockIdx.x * 32;   // k dim (512)
    #pragma unroll
    for (int i = threadIdx.y; i < 32; i += 8)
        tile[i][threadIdx.x] = src[(r0 + i)*HD + c0 + threadIdx.x];
    __syncthreads();
    #pragma unroll
    for (int i = threadIdx.y; i < 32; i += 8)
        dst[(c0 + i)*H5 + r0 + threadIdx.x] = tile[threadIdx.x][i];
}

// Launch #1: leaves + combined bias.
__global__ void initK(const float* __restrict__ seqt,
                      const float* __restrict__ bi,
                      const float* __restrict__ bs) {
    int idx = blockIdx.x*256 + threadIdx.x;
    if (idx < BD*NW*HD) {
        int i = idx % HD;
        int w = (idx / HD) % NW;
        int b = idx / (HD*NW);
        int c = cellIdx(b, w, 0);
        g_chartH[(size_t)c*HD + i] = seqt[(b*NW + w)*H2 + i];
        g_chartC[(size_t)c*HD + i] = seqt[(b*NW + w)*H2 + HD + i];
        if (i == 0) g_chartS[c] = 0.0f;
    }
    if (idx < H5) {
        float extra = (idx >= HD && idx < 3*HD) ? 1.0f : 0.0f;
        g_bias[idx] = bi[idx] + bs[idx] + extra;
    }
}

// Launch #2: copy Wbil into padded g_Wb.
__global__ void copyWbK(const float* __restrict__ Wbil) {
    int idx = blockIdx.x*256 + threadIdx.x;   // H2*H2 = 1M elements
    g_Wb[idx] = Wbil[idx];
}

// ---------------------------------------------------------------------------
// Per-cell projection GEMM. 1 output col per thread x CT cells.
// Output col space: [Ui 0..2559 | Us 2560..5119 | aL 5120..6143] = 24 x 256.
// grid (24, ceil(M/CT)), 256 threads. 8-deep branch-free weight prefetch.
// Launch #3 (L=0) is the ncu capture target.
// ---------------------------------------------------------------------------
template<int CT>
__global__ void __launch_bounds__(256) projK(int L, int P) {
    const int colBase = blockIdx.x * 256;
    const int M = BD*P;
    const int cbase = blockIdx.y * CT;

    const float* W; int seg, ncols, K, shift;
    if (colBase < H5)        { W = g_WiT; seg = 0;    ncols = H5; K = HD; shift = 9;  }
    else if (colBase < 2*H5) { W = g_WsT; seg = H5;   ncols = H5; K = HD; shift = 9;  }
    else                     { W = g_Wb;  seg = 2*H5; ncols = H2; K = H2; shift = 10; }
    const bool bil = (shift == 10);

    __shared__ float xs[CT][H2];
    for (int t = threadIdx.x; t < CT*K; t += 256) {
        int c = t >> shift, i = t & (K - 1);
        float v = 0.0f;
        int cell = cbase + c;
        if (cell < M) {
            int b = cell / P, left = cell - b*P;
            int ci = cellIdx(b, left, L);
            if (!bil) v = g_chartH[(size_t)ci*HD + i];
            else      v = (i < HD) ? g_chartH[(size_t)ci*HD + i]
                                   : g_chartC[(size_t)ci*HD + (i - HD)];
        }
        xs[c][i] = v;
    }
    __syncthreads();

    const int wcol = (colBase - seg) + threadIdx.x;
    const float* wp = W + wcol;
    const size_t ws = (size_t)ncols;

    float acc[CT];
    #pragma unroll
    for (int c = 0; c < CT; c++) acc[c] = 0.0f;

    float wc[8], wn[8];
    #pragma unroll
    for (int j = 0; j < 8; j++) wc[j] = wp[(size_t)j * ws];

    for (int k = 0; k < K; k += 8) {
        // prefetch next 8 weight rows (always in-bounds: KPAD=16)
        #pragma unroll
        for (int j = 0; j < 8; j++) wn[j] = wp[(size_t)(k + 8 + j) * ws];

        #pragma unroll
        for (int c0 = 0; c0 < CT; c0 += 2) {
            float4 xa0 = *(const float4*)&xs[c0][k];
            float4 xb0 = *(const float4*)&xs[c0][k + 4];
            if (CT > 1) {
                float4 xa1 = *(const float4*)&xs[c0 + 1][k];
                float4 xb1 = *(const float4*)&xs[c0 + 1][k + 4];
                acc[c0]   = fmaf(wc[0], xa0.x, acc[c0]);
                acc[c0+1] = fmaf(wc[0], xa1.x, acc[c0+1]);
                acc[c0]   = fmaf(wc[1], xa0.y, acc[c0]);
                acc[c0+1] = fmaf(wc[1], xa1.y, acc[c0+1]);
                acc[c0]   = fmaf(wc[2], xa0.z, acc[c0]);
                acc[c0+1] = fmaf(wc[2], xa1.z, acc[c0+1]);
                acc[c0]   = fmaf(wc[3], xa0.w, acc[c0]);
                acc[c0+1] = fmaf(wc[3], xa1.w, acc[c0+1]);
                acc[c0]   = fmaf(wc[4], xb0.x, acc[c0]);
                acc[c0+1] = fmaf(wc[4], xb1.x, acc[c0+1]);
                acc[c0]   = fmaf(wc[5], xb0.y, acc[c0]);
                acc[c0+1] = fmaf(wc[5], xb1.y, acc[c0+1]);
                acc[c0]   = fmaf(wc[6], xb0.z, acc[c0]);
                acc[c0+1] = fmaf(wc[6], xb1.z, acc[c0+1]);
                acc[c0]   = fmaf(wc[7], xb0.w, acc[c0]);
                acc[c0+1] = fmaf(wc[7], xb1.w, acc[c0+1]);
            } else {
                acc[c0] = fmaf(wc[0], xa0.x, acc[c0]);
                acc[c0] = fmaf(wc[1], xa0.y, acc[c0]);
                acc[c0] = fmaf(wc[2], xa0.z, acc[c0]);
                acc[c0] = fmaf(wc[3], xa0.w, acc[c0]);
                acc[c0] = fmaf(wc[4], xb0.x, acc[c0]);
                acc[c0] = fmaf(wc[5], xb0.y, acc[c0]);
                acc[c0] = fmaf(wc[6], xb0.z, acc[c0]);
                acc[c0] = fmaf(wc[7], xb0.w, acc[c0]);
            }
        }
        #pragma unroll
        for (int j = 0; j < 8; j++) wc[j] = wn[j];
    }

    float* dst; size_t stride;
    if (seg == 0)       { dst = g_Ui; stride = H5; }
    else if (seg == H5) { dst = g_Us; stride = H5; }
    else                { dst = g_aL; stride = H2; }

    #pragma unroll
    for (int c = 0; c < CT; c++) {
        int cell = cbase + c;
        if (cell < M) {
            int b = cell / P, left = cell - b*P;
            int ci = cellIdx(b, left, L);
            dst[(size_t)ci*stride + wcol] = acc[c];
        }
    }
}

// ---------------------------------------------------------------------------
// Pairs kernel: compat + softmax + gated combine.
// grid = BD*P*SPLIT blocks of (HD/SPLIT) threads; block owns span + e-chunk.
// ---------------------------------------------------------------------------
__global__ void pairsK(int L, int SPLIT, float* __restrict__ out) {
    const int P = NW - L;
    const int npair = BD*P;
    const int pairId = blockIdx.x % npair;
    const int s = blockIdx.x / npair;
    const int b = pairId / P, left = pairId - b*P;
    const int chunk = blockDim.x;
    const int e0 = s * chunk;

    __shared__ float s_w[24];
    __shared__ float s_comp[24];
    __shared__ int   s_offL[24], s_offR[24];

    const int tid = threadIdx.x, warp = tid >> 5, lane = tid & 31;
    const int nw = blockDim.x >> 5;

    // pass 1: compat_k = aL(left,k) . [rH;rC] + lS + rS
    for (int k = warp; k < L; k += nw) {
        int r = left + k + 1, rl = L - 1 - k;
        int cl = cellIdx(b, left, k), cr = cellIdx(b, r, rl);
        const float* a  = g_aL     + (size_t)cl*H2;
        const float* rh = g_chartH + (size_t)cr*HD;
        const float* rc = g_chartC + (size_t)cr*HD;
        float acc = 0.0f;
        for (int i = lane; i < HD; i += 32)
            acc = fmaf(a[i], rh[i], fmaf(a[HD + i], rc[i], acc));
        #pragma unroll
        for (int off = 16; off; off >>= 1)
            acc += __shfl_down_sync(0xffffffffu, acc, off);
        if (lane == 0) {
            s_comp[k] = acc + g_chartS[cl] + g_chartS[cr];
            s_offL[k] = cl; s_offR[k] = cr;
        }
    }
    __syncthreads();

    // softmax over k (warp 0)
    if (warp == 0) {
        float c = (lane < L) ? s_comp[lane] : -3.402823466e38f;
        float m = c;
        #pragma unroll
        for (int off = 16; off; off >>= 1)
            m = fmaxf(m, __shfl_xor_sync(0xffffffffu, m, off));
        float e = (lane < L) ? __expf(c - m) : 0.0f;
        float ssum = e;
        #pragma unroll
        for (int off = 16; off; off >>= 1)
            ssum += __shfl_xor_sync(0xffffffffu, ssum, off);
        float w = __fdividef(e, ssum);
        if (lane < L) s_w[lane] = w;
        float sn = (lane < L) ? w * c : 0.0f;
        #pragma unroll
        for (int off = 16; off; off >>= 1)
            sn += __shfl_xor_sync(0xffffffffu, sn, off);
        if (lane == 0 && s == 0) g_chartS[cellIdx(b, left, L)] = sn;
    }
    __syncthreads();

    // pass 2: gates + weighted combine for this block's e-chunk
    {
        int e = e0 + tid;
        float b0 = g_bias[e],        b1 = g_bias[HD + e],  b2 = g_bias[2*HD + e];
        float b3 = g_bias[3*HD + e], b4 = g_bias[4*HD + e];
        float ah = 0.0f, ac = 0.0f;
        for (int k = 0; k < L; k++) {
            int cl = s_offL[k], cr = s_offR[k];
            const float* ui = g_Ui + (size_t)cl*H5;
            const float* us = g_Us + (size_t)cr*H5;
            float p0 = ui[e]        + us[e]        + b0;
            float p1 = ui[HD + e]   + us[HD + e]   + b1;
            float p2 = ui[2*HD + e] + us[2*HD + e] + b2;
            float p3 = ui[3*HD + e] + us[3*HD + e] + b3;
            float p4 = ui[4*HD + e] + us[4*HD + e] + b4;
            float lc = g_chartC[(size_t)cl*HD + e];
            float rc = g_chartC[(size_t)cr*HD + e];
            float ig = sigf(p0), lf = sigf(p1), rf = sigf(p2), og = sigf(p4);
            float gg = tanhx(p3);
            float mem = fmaf(lf, lc, fmaf(rf, rc, ig * gg));
            float hh = og * tanhx(mem);
            float w = s_w[k];
            ah = fmaf(w, hh, ah);
            ac = fmaf(w, mem, ac);
        }
        int cn = cellIdx(b, left, L);
        g_chartH[(size_t)cn*HD + e] = ah;
        g_chartC[(size_t)cn*HD + e] = ac;
        if (out) {
            out[b*H2 + e]      = ah;
            out[b*H2 + HD + e] = ac;
        }
    }
}

// ---------------------------------------------------------------------------
// Host side
// ---------------------------------------------------------------------------
static void launchProj(int L, int P) {
    int M = BD * P;
    if (M >= 8)      projK<8><<<dim3(24, (M + 7) / 8), 256>>>(L, P);
    else             projK<4><<<dim3(24, 1),           256>>>(L, P);
}

static int pickSplit(int P) {
    int np = BD * P;
    if (np >= 64) return 4;   // chunk 128
    return 8;                 // chunk 64
}

extern "C" void kernel_launch(void* const* d_in, const int* in_sizes, int n_in,
                              void* d_out, int out_size) {
    const float* seqt = (const float*)d_in[0];
    const float* Wi   = (const float*)d_in[1];
    const float* bi   = (const float*)d_in[2];
    const float* Ws   = (const float*)d_in[3];
    const float* bs   = (const float*)d_in[4];
    const float* Wbil = (const float*)d_in[5];
    float* out = (float*)d_out;

    // Exactly 3 setup launches => ncu capture (0-based launch #3) = projK(L=0)
    transposeK<<<dim3(16, 80, 2), dim3(32, 8)>>>(Wi, Ws);   // #0
    initK<<<192, 256>>>(seqt, bi, bs);                      // #1
    copyWbK<<<(H2*H2)/256, 256>>>(Wbil);                    // #2

    launchProj(0, NW);                                      // #3  (M = 96)

    for (int L = 1; L < NW; L++) {
        int P = NW - L;
        int SPLIT = pickSplit(P);
        pairsK<<<BD*P*SPLIT, HD/SPLIT>>>(L, SPLIT, (L == NW - 1) ? out : nullptr);
        if (L < NW - 1) launchProj(L, P);
    }
}

// round 5
// speedup vs baseline: 2.1374x; 1.6469x over previous
#include <cuda_runtime.h>

// Problem constants (DioLstm: B=4, NWORD=24, HID=512)
#define BD 4
#define NW 24
#define HD 512
#define H2 1024
#define H5 2560
#define KPAD 16

// Chart state + per-cell projections (device globals; no allocs).
__device__ float g_chartH[BD*NW*NW*HD];
__device__ float g_chartC[BD*NW*NW*HD];
__device__ float g_chartS[BD*NW*NW];
__device__ float g_Ui[BD*NW*NW*H5];          // Wi @ h   per cell
__device__ float g_Us[BD*NW*NW*H5];          // Ws @ h   per cell
__device__ float g_aL[BD*NW*NW*H2];          // [h;c]^T @ Wbil per cell
__device__ float g_WiT[(HD+KPAD)*H5];        // Wi^T : [k][o], K-padded
__device__ float g_WsT[(HD+KPAD)*H5];
__device__ float g_Wb [(H2+KPAD)*H2];        // Wbil copy, K-padded
__device__ float g_bias[H5];                 // bi + bs + ins_bias
__device__ float g_part[256*6144];           // K-split partials (max 256 slots)

__device__ __forceinline__ int cellIdx(int b, int left, int len) {
    return (b*NW + left)*NW + len;
}

__device__ __forceinline__ float sigf(float x) {
    return __fdividef(1.0f, 1.0f + __expf(-x));
}
__device__ __forceinline__ float tanhx(float x) {
    return __fdividef(2.0f, 1.0f + __expf(-2.0f*x)) - 1.0f;
}

// ---------------------------------------------------------------------------
// Launch #0: transpose Wi/Ws ([5H,H] -> [H,5H]) into padded arrays.
// ---------------------------------------------------------------------------
__global__ void transposeK(const float* __restrict__ Wi, const float* __restrict__ Ws) {
    __shared__ float tile[32][33];
    const float* src = blockIdx.z ? Ws : Wi;
    float* dst = blockIdx.z ? g_WsT : g_WiT;
    int r0 = blockIdx.y * 32;   // o dim (2560)
    int c0 = blockIdx.x * 32;   // k dim (512)
    #pragma unroll
    for (int i = threadIdx.y; i < 32; i += 8)
        tile[i][threadIdx.x] = src[(r0 + i)*HD + c0 + threadIdx.x];
    __syncthreads();
    #pragma unroll
    for (int i = threadIdx.y; i < 32; i += 8)
        dst[(c0 + i)*H5 + r0 + threadIdx.x] = tile[threadIdx.x][i];
}

// Launch #1: leaves + combined bias.
__global__ void initK(const float* __restrict__ seqt,
                      const float* __restrict__ bi,
                      const float* __restrict__ bs) {
    int idx = blockIdx.x*256 + threadIdx.x;
    if (idx < BD*NW*HD) {
        int i = idx % HD;
        int w = (idx / HD) % NW;
        int b = idx / (HD*NW);
        int c = cellIdx(b, w, 0);
        g_chartH[(size_t)c*HD + i] = seqt[(b*NW + w)*H2 + i];
        g_chartC[(size_t)c*HD + i] = seqt[(b*NW + w)*H2 + HD + i];
        if (i == 0) g_chartS[c] = 0.0f;
    }
    if (idx < H5) {
        float extra = (idx >= HD && idx < 3*HD) ? 1.0f : 0.0f;
        g_bias[idx] = bi[idx] + bs[idx] + extra;
    }
}

// Launch #2: copy Wbil into padded g_Wb.
__global__ void copyWbK(const float* __restrict__ Wbil) {
    int idx = blockIdx.x*256 + threadIdx.x;   // H2*H2 = 1M elements
    g_Wb[idx] = Wbil[idx];
}

// ---------------------------------------------------------------------------
// Per-cell projection GEMM, K-split across blockIdx.z.
// 1 output col per thread x 8 cells, this block covers K rows
// [z*KS, (z+1)*KS). 2-batch-deep (16 row) branch-free weight prefetch.
// Output col space: [Ui 0..2559 | Us 2560..5119 | aL 5120..6143] = 24 x 256.
// grid (24, ceil(M/8), S), 256 threads. Partials -> g_part[slot][col].
// ---------------------------------------------------------------------------
__global__ void __launch_bounds__(256) projK(int L, int P, int log2S) {
    const int colBase = blockIdx.x * 256;
    const int M = BD*P;
    const int cbase = blockIdx.y * 8;
    const int z = blockIdx.z;

    const float* W; int seg, ncols, logK;
    if (colBase < H5)        { W = g_WiT; seg = 0;    ncols = H5; logK = 9;  }
    else if (colBase < 2*H5) { W = g_WsT; seg = H5;   ncols = H5; logK = 9;  }
    else                     { W = g_Wb;  seg = 2*H5; ncols = H2; logK = 10; }
    const int logKS = logK - log2S;
    const int KS = 1 << logKS;               // >= 32
    const int kbeg = z << logKS;
    const bool bil = (logK == 10);

    // stage this split's activation rows: xs[c][0..KS)
    __shared__ float xs[8][512];
    for (int t = threadIdx.x; t < (8 << logKS); t += 256) {
        int c = t >> logKS, i = t & (KS - 1);
        float v = 0.0f;
        int cell = cbase + c;
        if (cell < M) {
            int b = cell / P, left = cell - b*P;
            int ci = cellIdx(b, left, L);
            int g = kbeg + i;
            if (!bil) v = g_chartH[(size_t)ci*HD + g];
            else      v = (g < HD) ? g_chartH[(size_t)ci*HD + g]
                                   : g_chartC[(size_t)ci*HD + (g - HD)];
        }
        xs[c][i] = v;
    }
    __syncthreads();

    const int wcol = (colBase - seg) + threadIdx.x;
    const float* wp = W + (size_t)kbeg * ncols + wcol;
    const size_t ws = (size_t)ncols;

    float acc[8];
    #pragma unroll
    for (int c = 0; c < 8; c++) acc[c] = 0.0f;

    float wa[8], wb[8];
    #pragma unroll
    for (int j = 0; j < 8; j++) wa[j] = wp[(size_t)j * ws];
    #pragma unroll
    for (int j = 0; j < 8; j++) wb[j] = wp[(size_t)(8 + j) * ws];

    for (int k = 0; k < KS; k += 8) {
        // prefetch 2 batches ahead (always in-bounds: KPAD=16)
        float wn[8];
        #pragma unroll
        for (int j = 0; j < 8; j++) wn[j] = wp[(size_t)(k + 16 + j) * ws];

        #pragma unroll
        for (int c0 = 0; c0 < 8; c0 += 2) {
            float4 xa0 = *(const float4*)&xs[c0][k];
            float4 xb0 = *(const float4*)&xs[c0][k + 4];
            float4 xa1 = *(const float4*)&xs[c0 + 1][k];
            float4 xb1 = *(const float4*)&xs[c0 + 1][k + 4];
            acc[c0]   = fmaf(wa[0], xa0.x, acc[c0]);
            acc[c0+1] = fmaf(wa[0], xa1.x, acc[c0+1]);
            acc[c0]   = fmaf(wa[1], xa0.y, acc[c0]);
            acc[c0+1] = fmaf(wa[1], xa1.y, acc[c0+1]);
            acc[c0]   = fmaf(wa[2], xa0.z, acc[c0]);
            acc[c0+1] = fmaf(wa[2], xa1.z, acc[c0+1]);
            acc[c0]   = fmaf(wa[3], xa0.w, acc[c0]);
            acc[c0+1] = fmaf(wa[3], xa1.w, acc[c0+1]);
            acc[c0]   = fmaf(wa[4], xb0.x, acc[c0]);
            acc[c0+1] = fmaf(wa[4], xb1.x, acc[c0+1]);
            acc[c0]   = fmaf(wa[5], xb0.y, acc[c0]);
            acc[c0+1] = fmaf(wa[5], xb1.y, acc[c0+1]);
            acc[c0]   = fmaf(wa[6], xb0.z, acc[c0]);
            acc[c0+1] = fmaf(wa[6], xb1.z, acc[c0+1]);
            acc[c0]   = fmaf(wa[7], xb0.w, acc[c0]);
            acc[c0+1] = fmaf(wa[7], xb1.w, acc[c0+1]);
        }
        #pragma unroll
        for (int j = 0; j < 8; j++) { wa[j] = wb[j]; wb[j] = wn[j]; }
    }

    // write partials: slot = z * (tiles*8) + cell
    const int tiles8 = gridDim.y * 8;
    float* pp = g_part + ((size_t)(z * tiles8 + cbase)) * 6144
                       + colBase + threadIdx.x;
    #pragma unroll
    for (int c = 0; c < 8; c++) {
        if (cbase + c < M) pp[(size_t)c * 6144] = acc[c];
    }
}

// ---------------------------------------------------------------------------
// Sum the S K-split partials into g_Ui / g_Us / g_aL.
// grid = ceil(M*6144/256) x 256.
// ---------------------------------------------------------------------------
__global__ void reduceK(int L, int P, int tiles8, int S) {
    int idx = blockIdx.x*256 + threadIdx.x;
    int M = BD*P;
    if (idx >= M*6144) return;
    int cell = idx / 6144, col = idx - cell*6144;
    float s = 0.0f;
    for (int z = 0; z < S; z++)
        s += g_part[((size_t)(z*tiles8 + cell))*6144 + col];
    int b = cell / P, left = cell - b*P;
    int ci = cellIdx(b, left, L);
    if (col < H5)        g_Ui[(size_t)ci*H5 + col]          = s;
    else if (col < 2*H5) g_Us[(size_t)ci*H5 + (col - H5)]   = s;
    else                 g_aL[(size_t)ci*H2 + (col - 2*H5)] = s;
}

// ---------------------------------------------------------------------------
// Pairs kernel: compat + softmax + gated combine.
// grid = BD*P*SPLIT blocks of (HD/SPLIT) threads; block owns span + e-chunk.
// ---------------------------------------------------------------------------
__global__ void pairsK(int L, int SPLIT, float* __restrict__ out) {
    const int P = NW - L;
    const int npair = BD*P;
    const int pairId = blockIdx.x % npair;
    const int s = blockIdx.x / npair;
    const int b = pairId / P, left = pairId - b*P;
    const int chunk = blockDim.x;
    const int e0 = s * chunk;

    __shared__ float s_w[24];
    __shared__ float s_comp[24];
    __shared__ int   s_offL[24], s_offR[24];

    const int tid = threadIdx.x, warp = tid >> 5, lane = tid & 31;
    const int nw = blockDim.x >> 5;

    // pass 1: compat_k = aL(left,k) . [rH;rC] + lS + rS
    for (int k = warp; k < L; k += nw) {
        int r = left + k + 1, rl = L - 1 - k;
        int cl = cellIdx(b, left, k), cr = cellIdx(b, r, rl);
        const float* a  = g_aL     + (size_t)cl*H2;
        const float* rh = g_chartH + (size_t)cr*HD;
        const float* rc = g_chartC + (size_t)cr*HD;
        float acc = 0.0f;
        for (int i = lane; i < HD; i += 32)
            acc = fmaf(a[i], rh[i], fmaf(a[HD + i], rc[i], acc));
        #pragma unroll
        for (int off = 16; off; off >>= 1)
            acc += __shfl_down_sync(0xffffffffu, acc, off);
        if (lane == 0) {
            s_comp[k] = acc + g_chartS[cl] + g_chartS[cr];
            s_offL[k] = cl; s_offR[k] = cr;
        }
    }
    __syncthreads();

    // softmax over k (warp 0)
    if (warp == 0) {
        float c = (lane < L) ? s_comp[lane] : -3.402823466e38f;
        float m = c;
        #pragma unroll
        for (int off = 16; off; off >>= 1)
            m = fmaxf(m, __shfl_xor_sync(0xffffffffu, m, off));
        float e = (lane < L) ? __expf(c - m) : 0.0f;
        float ssum = e;
        #pragma unroll
        for (int off = 16; off; off >>= 1)
            ssum += __shfl_xor_sync(0xffffffffu, ssum, off);
        float w = __fdividef(e, ssum);
        if (lane < L) s_w[lane] = w;
        float sn = (lane < L) ? w * c : 0.0f;
        #pragma unroll
        for (int off = 16; off; off >>= 1)
            sn += __shfl_xor_sync(0xffffffffu, sn, off);
        if (lane == 0 && s == 0) g_chartS[cellIdx(b, left, L)] = sn;
    }
    __syncthreads();

    // pass 2: gates + weighted combine for this block's e-chunk
    {
        int e = e0 + tid;
        float b0 = g_bias[e],        b1 = g_bias[HD + e],  b2 = g_bias[2*HD + e];
        float b3 = g_bias[3*HD + e], b4 = g_bias[4*HD + e];
        float ah = 0.0f, ac = 0.0f;
        for (int k = 0; k < L; k++) {
            int cl = s_offL[k], cr = s_offR[k];
            const float* ui = g_Ui + (size_t)cl*H5;
            const float* us = g_Us + (size_t)cr*H5;
            float p0 = ui[e]        + us[e]        + b0;
            float p1 = ui[HD + e]   + us[HD + e]   + b1;
            float p2 = ui[2*HD + e] + us[2*HD + e] + b2;
            float p3 = ui[3*HD + e] + us[3*HD + e] + b3;
            float p4 = ui[4*HD + e] + us[4*HD + e] + b4;
            float lc = g_chartC[(size_t)cl*HD + e];
            float rc = g_chartC[(size_t)cr*HD + e];
            float ig = sigf(p0), lf = sigf(p1), rf = sigf(p2), og = sigf(p4);
            float gg = tanhx(p3);
            float mem = fmaf(lf, lc, fmaf(rf, rc, ig * gg));
            float hh = og * tanhx(mem);
            float w = s_w[k];
            ah = fmaf(w, hh, ah);
            ac = fmaf(w, mem, ac);
        }
        int cn = cellIdx(b, left, L);
        g_chartH[(size_t)cn*HD + e] = ah;
        g_chartC[(size_t)cn*HD + e] = ac;
        if (out) {
            out[b*H2 + e]      = ah;
            out[b*H2 + HD + e] = ac;
        }
    }
}

// ---------------------------------------------------------------------------
// Host side
// ---------------------------------------------------------------------------
static void launchProj(int L, int P) {
    int M = BD * P;
    int tiles = (M + 7) / 8;
    int S, l2s;
    if (tiles >= 9)      { S = 2;  l2s = 1; }
    else if (tiles >= 5) { S = 4;  l2s = 2; }
    else if (tiles >= 3) { S = 8;  l2s = 3; }
    else                 { S = 16; l2s = 4; }
    projK<<<dim3(24, tiles, S), 256>>>(L, P, l2s);
    reduceK<<<(M*6144 + 255)/256, 256>>>(L, P, tiles*8, S);
}

static int pickSplit(int P) {
    int np = BD * P;
    if (np >= 64) return 4;   // chunk 128
    return 8;                 // chunk 64
}

extern "C" void kernel_launch(void* const* d_in, const int* in_sizes, int n_in,
                              void* d_out, int out_size) {
    const float* seqt = (const float*)d_in[0];
    const float* Wi   = (const float*)d_in[1];
    const float* bi   = (const float*)d_in[2];
    const float* Ws   = (const float*)d_in[3];
    const float* bs   = (const float*)d_in[4];
    const float* Wbil = (const float*)d_in[5];
    float* out = (float*)d_out;

    // Exactly 3 setup launches => ncu capture (launch #3) = projK(L=0)
    transposeK<<<dim3(16, 80, 2), dim3(32, 8)>>>(Wi, Ws);   // #0
    initK<<<192, 256>>>(seqt, bi, bs);                      // #1
    copyWbK<<<(H2*H2)/256, 256>>>(Wbil);                    // #2

    launchProj(0, NW);                                      // #3 + #4

    for (int L = 1; L < NW; L++) {
        int P = NW - L;
        int SPLIT = pickSplit(P);
        pairsK<<<BD*P*SPLIT, HD/SPLIT>>>(L, SPLIT, (L == NW - 1) ? out : nullptr);
        if (L < NW - 1) launchProj(L, P);
    }
}

// round 7
// speedup vs baseline: 2.3582x; 1.1033x over previous
#include <cuda_runtime.h>

// Problem constants (DioLstm: B=4, NWORD=24, HID=512)
#define BD 4
#define NW 24
#define HD 512
#define H2 1024
#define H5 2560
#define KPAD 16

typedef unsigned long long u64;

// Chart state + per-cell projections (device globals; no allocs).
__device__ __align__(16) float g_chartH[BD*NW*NW*HD];
__device__ __align__(16) float g_chartC[BD*NW*NW*HD];
__device__ __align__(16) float g_chartS[BD*NW*NW];
__device__ __align__(16) float g_Ui[BD*NW*NW*H5];      // Wi @ h   per cell
__device__ __align__(16) float g_Us[BD*NW*NW*H5];      // Ws @ h   per cell
__device__ __align__(16) float g_aL[BD*NW*NW*H2];      // [h;c]^T @ Wbil per cell
__device__ __align__(16) float g_WiT[(HD+KPAD)*H5];    // Wi^T : [k][o], K-padded
__device__ __align__(16) float g_WsT[(HD+KPAD)*H5];
__device__ __align__(16) float g_Wb [(H2+KPAD)*H2];    // Wbil copy, K-padded
__device__ __align__(16) float g_bias[H5];             // bi + bs + ins_bias
__device__ __align__(16) float g_part[1024*6144];      // K-split partials (1024 slots)

__device__ __forceinline__ int cellIdx(int b, int left, int len) {
    return (b*NW + left)*NW + len;
}

__device__ __forceinline__ float sigf(float x) {
    return __fdividef(1.0f, 1.0f + __expf(-x));
}
__device__ __forceinline__ float tanhx(float x) {
    return __fdividef(2.0f, 1.0f + __expf(-2.0f*x)) - 1.0f;
}

// packed fp32x2 FMA: d = a*b + d   (SASS FFMA2; PTX-only form)
__device__ __forceinline__ void fma2(u64& d, u64 a, u64 b) {
    asm("fma.rn.f32x2 %0, %1, %2, %3;" : "=l"(d) : "l"(a), "l"(b), "l"(d));
}
__device__ __forceinline__ float2 u2f(u64 v) {
    float2 f;
    asm("mov.b64 {%0, %1}, %2;" : "=f"(f.x), "=f"(f.y) : "l"(v));
    return f;
}

// ---------------------------------------------------------------------------
// Launch #0: transpose Wi/Ws ([5H,H] -> [H,5H]) into padded arrays.
// ---------------------------------------------------------------------------
__global__ void transposeK(const float* __restrict__ Wi, const float* __restrict__ Ws) {
    __shared__ float tile[32][33];
    const float* src = blockIdx.z ? Ws : Wi;
    float* dst = blockIdx.z ? g_WsT : g_WiT;
    int r0 = blockIdx.y * 32;   // o dim (2560)
    int c0 = blockIdx.x * 32;   // k dim (512)
    #pragma unroll
    for (int i = threadIdx.y; i < 32; i += 8)
        tile[i][threadIdx.x] = src[(r0 + i)*HD + c0 + threadIdx.x];
    __syncthreads();
    #pragma unroll
    for (int i = threadIdx.y; i < 32; i += 8)
        dst[(c0 + i)*H5 + r0 + threadIdx.x] = tile[threadIdx.x][i];
}

// Launch #1: leaves + combined bias.
__global__ void initK(const float* __restrict__ seqt,
                      const float* __restrict__ bi,
                      const float* __restrict__ bs) {
    int idx = blockIdx.x*256 + threadIdx.x;
    if (idx < BD*NW*HD) {
        int i = idx % HD;
        int w = (idx / HD) % NW;
        int b = idx / (HD*NW);
        int c = cellIdx(b, w, 0);
        g_chartH[(size_t)c*HD + i] = seqt[(b*NW + w)*H2 + i];
        g_chartC[(size_t)c*HD + i] = seqt[(b*NW + w)*H2 + HD + i];
        if (i == 0) g_chartS[c] = 0.0f;
    }
    if (idx < H5) {
        float extra = (idx >= HD && idx < 3*HD) ? 1.0f : 0.0f;
        g_bias[idx] = bi[idx] + bs[idx] + extra;
    }
}

// Launch #2: copy Wbil into padded g_Wb.
__global__ void copyWbK(const float* __restrict__ Wbil) {
    int idx = blockIdx.x*256 + threadIdx.x;   // H2*H2 = 1M elements
    g_Wb[idx] = Wbil[idx];
}

// ---------------------------------------------------------------------------
// Per-cell projection GEMM, K-split, FFMA2 inner loop.
// Thread owns 4 output cols (two f32x2 lanes) x CT cells.
// Block: 128 threads -> 512 cols; col space 6144 = 12 tiles.
// grid (12, ceil(M/CT), S); this block reduces K rows [z*KS, (z+1)*KS).
// Weights: one LDG.128 per row -> 2 u64 FFMA2 operands (no packing).
// Activations: duplicated (x,x) float2 pairs in smem; one LDS.128 yields
// two ready b-operands. Partials -> g_part[slot][col].
// ---------------------------------------------------------------------------
template<int CT>
__global__ void __launch_bounds__(128) projK(int L, int P, int log2S) {
    const int colBase = blockIdx.x * 512;
    const int M = BD*P;
    const int cbase = blockIdx.y * CT;
    const int z = blockIdx.z;

    const float* W; int seg, ncols, logK;
    if (colBase < H5)        { W = g_WiT; seg = 0;    ncols = H5; logK = 9;  }
    else if (colBase < 2*H5) { W = g_WsT; seg = H5;   ncols = H5; logK = 9;  }
    else                     { W = g_Wb;  seg = 2*H5; ncols = H2; logK = 10; }
    const int logKS = logK - log2S;
    const int KS = 1 << logKS;               // >= 32, multiple of 8, <= 256
    const int kbeg = z << logKS;
    const bool bil = (logK == 10);

    // duplicated activations: xs2[c][i] = (x, x)
    __shared__ __align__(16) float2 xs2[CT][256];
    for (int t = threadIdx.x; t < (CT << logKS); t += 128) {
        int c = t >> logKS, i = t & (KS - 1);
        float v = 0.0f;
        int cell = cbase + c;
        if (cell < M) {
            int b = cell / P, left = cell - b*P;
            int ci = cellIdx(b, left, L);
            int g = kbeg + i;
            if (!bil) v = g_chartH[(size_t)ci*HD + g];
            else      v = (g < HD) ? g_chartH[(size_t)ci*HD + g]
                                   : g_chartC[(size_t)ci*HD + (g - HD)];
        }
        xs2[c][i] = make_float2(v, v);
    }
    __syncthreads();

    const int wcol = (colBase - seg) + 4*threadIdx.x;
    const char* wbase = (const char*)(W + (size_t)kbeg * ncols + wcol);
    const size_t wstride = (size_t)ncols * 4;   // bytes per K row

    u64 aLo[CT], aHi[CT];
    #pragma unroll
    for (int c = 0; c < CT; c++) { aLo[c] = 0ull; aHi[c] = 0ull; }

    ulonglong2 wA[4], wB[4];
    #pragma unroll
    for (int j = 0; j < 4; j++)
        wA[j] = *(const ulonglong2*)(wbase + (size_t)j * wstride);

    for (int k = 0; k < KS; k += 8) {
        #pragma unroll
        for (int j = 0; j < 4; j++)
            wB[j] = *(const ulonglong2*)(wbase + (size_t)(k + 4 + j) * wstride);

        #pragma unroll
        for (int c = 0; c < CT; c++) {
            ulonglong2 x01 = *(const ulonglong2*)&xs2[c][k];
            ulonglong2 x23 = *(const ulonglong2*)&xs2[c][k + 2];
            fma2(aLo[c], wA[0].x, x01.x);  fma2(aHi[c], wA[0].y, x01.x);
            fma2(aLo[c], wA[1].x, x01.y);  fma2(aHi[c], wA[1].y, x01.y);
            fma2(aLo[c], wA[2].x, x23.x);  fma2(aHi[c], wA[2].y, x23.x);
            fma2(aLo[c], wA[3].x, x23.y);  fma2(aHi[c], wA[3].y, x23.y);
        }

        #pragma unroll
        for (int j = 0; j < 4; j++)
            wA[j] = *(const ulonglong2*)(wbase + (size_t)(k + 8 + j) * wstride);

        #pragma unroll
        for (int c = 0; c < CT; c++) {
            ulonglong2 x01 = *(const ulonglong2*)&xs2[c][k + 4];
            ulonglong2 x23 = *(const ulonglong2*)&xs2[c][k + 6];
            fma2(aLo[c], wB[0].x, x01.x);  fma2(aHi[c], wB[0].y, x01.x);
            fma2(aLo[c], wB[1].x, x01.y);  fma2(aHi[c], wB[1].y, x01.y);
            fma2(aLo[c], wB[2].x, x23.x);  fma2(aHi[c], wB[2].y, x23.x);
            fma2(aLo[c], wB[3].x, x23.y);  fma2(aHi[c], wB[3].y, x23.y);
        }
    }

    // write partials: slot = z * (gridDim.y*CT) + cell
    const int slotStride = gridDim.y * CT;
    float* pp = g_part + ((size_t)(z * slotStride + cbase)) * 6144
                       + colBase + 4*threadIdx.x;
    #pragma unroll
    for (int c = 0; c < CT; c++) {
        if (cbase + c < M) {
            float2 lo = u2f(aLo[c]), hi = u2f(aHi[c]);
            *(float4*)(pp + (size_t)c * 6144) = make_float4(lo.x, lo.y, hi.x, hi.y);
        }
    }
}

// ---------------------------------------------------------------------------
// Sum the S K-split partials into g_Ui / g_Us / g_aL (float4 wide).
// ---------------------------------------------------------------------------
__global__ void reduceK(int L, int P, int slotStride, int S) {
    int idx = blockIdx.x*256 + threadIdx.x;
    int M = BD*P;
    if (idx >= M*1536) return;                  // 1536 float4 per cell
    int cell = idx / 1536, c4 = idx - cell*1536;
    int col = c4 * 4;
    float4 s = make_float4(0.f, 0.f, 0.f, 0.f);
    for (int z = 0; z < S; z++) {
        const float4 v = *(const float4*)&g_part[((size_t)(z*slotStride + cell))*6144 + col];
        s.x += v.x; s.y += v.y; s.z += v.z; s.w += v.w;
    }
    int b = cell / P, left = cell - b*P;
    int ci = cellIdx(b, left, L);
    if (col < H5)        *(float4*)&g_Ui[(size_t)ci*H5 + col]          = s;
    else if (col < 2*H5) *(float4*)&g_Us[(size_t)ci*H5 + (col - H5)]   = s;
    else                 *(float4*)&g_aL[(size_t)ci*H2 + (col - 2*H5)] = s;
}

// ---------------------------------------------------------------------------
// Pairs kernel: compat + softmax + gated combine.
// grid = BD*P*SPLIT blocks of (HD/SPLIT) threads; block owns span + e-chunk.
// ---------------------------------------------------------------------------
__global__ void pairsK(int L, int SPLIT, float* __restrict__ out) {
    const int P = NW - L;
    const int npair = BD*P;
    const int pairId = blockIdx.x % npair;
    const int s = blockIdx.x / npair;
    const int b = pairId / P, left = pairId - b*P;
    const int chunk = blockDim.x;
    const int e0 = s * chunk;

    __shared__ float s_w[24];
    __shared__ float s_comp[24];
    __shared__ int   s_offL[24], s_offR[24];

    const int tid = threadIdx.x, warp = tid >> 5, lane = tid & 31;
    const int nw = blockDim.x >> 5;

    // pass 1: compat_k = aL(left,k) . [rH;rC] + lS + rS
    for (int k = warp; k < L; k += nw) {
        int r = left + k + 1, rl = L - 1 - k;
        int cl = cellIdx(b, left, k), cr = cellIdx(b, r, rl);
        const float* a  = g_aL     + (size_t)cl*H2;
        const float* rh = g_chartH + (size_t)cr*HD;
        const float* rc = g_chartC + (size_t)cr*HD;
        float acc = 0.0f;
        for (int i = lane; i < HD; i += 32)
            acc = fmaf(a[i], rh[i], fmaf(a[HD + i], rc[i], acc));
        #pragma unroll
        for (int off = 16; off; off >>= 1)
            acc += __shfl_down_sync(0xffffffffu, acc, off);
        if (lane == 0) {
            s_comp[k] = acc + g_chartS[cl] + g_chartS[cr];
            s_offL[k] = cl; s_offR[k] = cr;
        }
    }
    __syncthreads();

    // softmax over k (warp 0)
    if (warp == 0) {
        float c = (lane < L) ? s_comp[lane] : -3.402823466e38f;
        float m = c;
        #pragma unroll
        for (int off = 16; off; off >>= 1)
            m = fmaxf(m, __shfl_xor_sync(0xffffffffu, m, off));
        float e = (lane < L) ? __expf(c - m) : 0.0f;
        float ssum = e;
        #pragma unroll
        for (int off = 16; off; off >>= 1)
            ssum += __shfl_xor_sync(0xffffffffu, ssum, off);
        float w = __fdividef(e, ssum);
        if (lane < L) s_w[lane] = w;
        float sn = (lane < L) ? w * c : 0.0f;
        #pragma unroll
        for (int off = 16; off; off >>= 1)
            sn += __shfl_xor_sync(0xffffffffu, sn, off);
        if (lane == 0 && s == 0) g_chartS[cellIdx(b, left, L)] = sn;
    }
    __syncthreads();

    // pass 2: gates + weighted combine for this block's e-chunk
    {
        int e = e0 + tid;
        float b0 = g_bias[e],        b1 = g_bias[HD + e],  b2 = g_bias[2*HD + e];
        float b3 = g_bias[3*HD + e], b4 = g_bias[4*HD + e];
        float ah = 0.0f, ac = 0.0f;
        for (int k = 0; k < L; k++) {
            int cl = s_offL[k], cr = s_offR[k];
            const float* ui = g_Ui + (size_t)cl*H5;
            const float* us = g_Us + (size_t)cr*H5;
            float p0 = ui[e]        + us[e]        + b0;
            float p1 = ui[HD + e]   + us[HD + e]   + b1;
            float p2 = ui[2*HD + e] + us[2*HD + e] + b2;
            float p3 = ui[3*HD + e] + us[3*HD + e] + b3;
            float p4 = ui[4*HD + e] + us[4*HD + e] + b4;
            float lc = g_chartC[(size_t)cl*HD + e];
            float rc = g_chartC[(size_t)cr*HD + e];
            float ig = sigf(p0), lf = sigf(p1), rf = sigf(p2), og = sigf(p4);
            float gg = tanhx(p3);
            float mem = fmaf(lf, lc, fmaf(rf, rc, ig * gg));
            float hh = og * tanhx(mem);
            float w = s_w[k];
            ah = fmaf(w, hh, ah);
            ac = fmaf(w, mem, ac);
        }
        int cn = cellIdx(b, left, L);
        g_chartH[(size_t)cn*HD + e] = ah;
        g_chartC[(size_t)cn*HD + e] = ac;
        if (out) {
            out[b*H2 + e]      = ah;
            out[b*H2 + HD + e] = ac;
        }
    }
}

// ---------------------------------------------------------------------------
// Host side
// ---------------------------------------------------------------------------
static void launchProj(int L, int P) {
    int M = BD * P;
    int CT = (M >= 64) ? 8 : (M >= 24) ? 4 : 2;
    int tiles = (M + CT - 1) / CT;
    int S = 1, l2s = 0;
    // grow S for occupancy, but never exceed 1024 scratch slots
    while (12 * tiles * S < 512 && S < 16 && 2 * S * tiles * CT <= 1024) {
        S <<= 1; l2s++;
    }
    if (CT == 8)      projK<8><<<dim3(12, tiles, S), 128>>>(L, P, l2s);
    else if (CT == 4) projK<4><<<dim3(12, tiles, S), 128>>>(L, P, l2s);
    else              projK<2><<<dim3(12, tiles, S), 128>>>(L, P, l2s);
    reduceK<<<(M*1536 + 255)/256, 256>>>(L, P, tiles*CT, S);
}

static int pickSplit(int P) {
    int np = BD * P;
    if (np >= 64) return 4;   // chunk 128
    return 8;                 // chunk 64
}

extern "C" void kernel_launch(void* const* d_in, const int* in_sizes, int n_in,
                              void* d_out, int out_size) {
    const float* seqt = (const float*)d_in[0];
    const float* Wi   = (const float*)d_in[1];
    const float* bi   = (const float*)d_in[2];
    const float* Ws   = (const float*)d_in[3];
    const float* bs   = (const float*)d_in[4];
    const float* Wbil = (const float*)d_in[5];
    float* out = (float*)d_out;

    // Exactly 3 setup launches => ncu capture (launch #3) = projK(L=0)
    transposeK<<<dim3(16, 80, 2), dim3(32, 8)>>>(Wi, Ws);   // #0
    initK<<<192, 256>>>(seqt, bi, bs);                      // #1
    copyWbK<<<(H2*H2)/256, 256>>>(Wbil);                    // #2

    launchProj(0, NW);                                      // #3 + #4

    for (int L = 1; L < NW; L++) {
        int P = NW - L;
        int SPLIT = pickSplit(P);
        pairsK<<<BD*P*SPLIT, HD/SPLIT>>>(L, SPLIT, (L == NW - 1) ? out : nullptr);
        if (L < NW - 1) launchProj(L, P);
    }
}